// round 13
// baseline (speedup 1.0000x reference)
#include <cuda_runtime.h>
#include <cstdint>

#define TT 256
#define CC 195
#define HH 8
#define JJ 24            // qkv output cols: q(0-7) k(8-15) v(16-23)
#define NT 128
#define KPAD 200         // K padded to 25 chunks of 8
#define NCH 25
#define XSTR 12          // floats per row in x chunk buffer (48B: 16B-aligned, LDSM banks 12r%32 distinct)
#define XB (64 * XSTR)   // 768 floats per warp buffer
#define WFLOATS (KPAD * JJ)  // 4800
#define QKVSTR 28        // qkv smem row stride (112B: 16B-aligned rows)

typedef unsigned long long u64;

__device__ __forceinline__ u64 pack2(float v) {
    u64 r; asm("mov.b64 %0, {%1, %1};" : "=l"(r) : "f"(v)); return r;
}
__device__ __forceinline__ u64 pack2f(float lo, float hi) {
    u64 r; asm("mov.b64 %0, {%1, %2};" : "=l"(r) : "f"(lo), "f"(hi)); return r;
}
__device__ __forceinline__ void unpack2(u64 v, float& lo, float& hi) {
    asm("mov.b64 {%0, %1}, %2;" : "=f"(lo), "=f"(hi) : "l"(v));
}
__device__ __forceinline__ void ffma2(u64& d, u64 a, u64 b) {
    asm("fma.rn.f32x2 %0, %1, %2, %0;" : "+l"(d) : "l"(a), "l"(b));
}
__device__ __forceinline__ u64 mul2(u64 a, u64 b) {
    u64 r; asm("mul.rn.f32x2 %0, %1, %2;" : "=l"(r) : "l"(a), "l"(b)); return r;
}
__device__ __forceinline__ uint32_t f2tf32(float f) {
    uint32_t r; asm("cvt.rna.tf32.f32 %0, %1;" : "=r"(r) : "f"(f)); return r;
}
__device__ __forceinline__ void ldsm4(uint32_t* d, unsigned addr) {
    asm volatile("ldmatrix.sync.aligned.m8n8.x4.shared.b16 {%0,%1,%2,%3}, [%4];"
                 : "=r"(d[0]), "=r"(d[1]), "=r"(d[2]), "=r"(d[3]) : "r"(addr));
}
__device__ __forceinline__ void mma_tf32(float* c, const uint32_t* a, const uint32_t* b) {
    asm volatile("mma.sync.aligned.m16n8k8.row.col.f32.tf32.tf32.f32 "
                 "{%0,%1,%2,%3}, {%4,%5,%6,%7}, {%8,%9}, {%0,%1,%2,%3};"
                 : "+f"(c[0]), "+f"(c[1]), "+f"(c[2]), "+f"(c[3])
                 : "r"(a[0]), "r"(a[1]), "r"(a[2]), "r"(a[3]), "r"(b[0]), "r"(b[1]));
}

__global__ __launch_bounds__(NT, 4)
void head_attn_kernel(const float* __restrict__ x,
                      const float* __restrict__ Wq,
                      const float* __restrict__ Wk,
                      const float* __restrict__ Wv,
                      float* __restrict__ out)
{
    // phase A: [ w_s (19200B) | 4 warps x 2 x chunk buf (3072B each) ] = 43776B
    // phase B: qkv_s [256][28] f32 (28672B) overlays from offset 0
    __shared__ __align__(16) float smem[WFLOATS + 8 * XB];
    float* w_s = smem;

    const int tid = threadIdx.x;
    const int b   = blockIdx.x;
    const int w   = tid >> 5;
    const int l   = tid & 31;

    // ---- stage W as [c][24], rows >= CC zeroed (K padding) ----
    for (int i = tid; i < KPAD * HH; i += NT) {
        int c = i >> 3, h = i & 7;
        float vq = 0.f, vk = 0.f, vv = 0.f;
        if (c < CC) { vq = Wq[c * HH + h]; vk = Wk[c * HH + h]; vv = Wv[c * HH + h]; }
        w_s[c * JJ +      h] = vq;
        w_s[c * JJ +  8 + h] = vk;
        w_s[c * JJ + 16 + h] = vv;
    }

    // ---- phase 1: tf32 MMA projection, warp-private pipelined x staging ----
    // warp w owns global rows b*256 + 64w .. +63; lane stages rows 2l, 2l+1
    const float* xg = x + ((long)b * TT + 64 * w) * CC;
    const int r0 = 2 * l, r1 = 2 * l + 1;
    float* buf0 = smem + WFLOATS + w * 2 * XB;

    float rr[16];
    #pragma unroll
    for (int j = 0; j < 8; j++) {
        rr[j]     = __ldg(&xg[(long)r0 * CC + j]);
        rr[8 + j] = __ldg(&xg[(long)r1 * CC + j]);
    }
    *reinterpret_cast<float4*>(&buf0[r0 * XSTR])     = make_float4(rr[0], rr[1], rr[2], rr[3]);
    *reinterpret_cast<float4*>(&buf0[r0 * XSTR + 4]) = make_float4(rr[4], rr[5], rr[6], rr[7]);
    *reinterpret_cast<float4*>(&buf0[r1 * XSTR])     = make_float4(rr[8], rr[9], rr[10], rr[11]);
    *reinterpret_cast<float4*>(&buf0[r1 * XSTR + 4]) = make_float4(rr[12], rr[13], rr[14], rr[15]);
    __syncthreads();   // w_s + chunk 0 ready

    float cacc[48];    // [mt 0..3][nt 0..2][4]
    #pragma unroll
    for (int i = 0; i < 48; i++) cacc_init: cacc[i] = 0.f;

    // LDSM lane address components (within chunk buffer)
    const unsigned lrow = (l & 7) + 8 * ((l >> 3) & 1);  // row within m16 tile
    const unsigned lcolo = (l >> 4) * 16;                // 0 or 16B (cols 4-7)
    // B fragment indices
    const int bk = l & 3;    // k within chunk (and +4)
    const int bn = l >> 2;   // n within n8 tile

    #pragma unroll 1
    for (int ch = 0; ch < NCH; ch++) {
        float* cur = smem + WFLOATS + w * 2 * XB + (ch & 1) * XB;
        float* nxt = smem + WFLOATS + w * 2 * XB + ((ch + 1) & 1) * XB;

        // prefetch next chunk into registers (tail chunk: 3 valid cols + zeros)
        if (ch + 1 < NCH) {
            const int c0 = (ch + 1) * 8;
            if (ch + 1 < NCH - 1) {
                #pragma unroll
                for (int j = 0; j < 8; j++) {
                    rr[j]     = __ldg(&xg[(long)r0 * CC + c0 + j]);
                    rr[8 + j] = __ldg(&xg[(long)r1 * CC + c0 + j]);
                }
            } else {
                #pragma unroll
                for (int j = 0; j < 8; j++) {
                    rr[j]     = (j < 3) ? __ldg(&xg[(long)r0 * CC + c0 + j]) : 0.f;
                    rr[8 + j] = (j < 3) ? __ldg(&xg[(long)r1 * CC + c0 + j]) : 0.f;
                }
            }
        }

        // B fragments: k rows ch*8+bk, +4; cols 8nt+bn  (conflict-free LDS.32)
        const int kr = ch * 8 + bk;
        uint32_t bh[6];
        #pragma unroll
        for (int nt = 0; nt < 3; nt++) {
            bh[2 * nt]     = f2tf32(w_s[kr * JJ       + nt * 8 + bn]);
            bh[2 * nt + 1] = f2tf32(w_s[(kr + 4) * JJ + nt * 8 + bn]);
        }

        // A fragments via ldmatrix (b16 view of tf32 tile) + MMAs
        unsigned abase = (unsigned)__cvta_generic_to_shared(cur) + lrow * (XSTR * 4) + lcolo;
        #pragma unroll
        for (int mt = 0; mt < 4; mt++) {
            uint32_t ua[4];
            ldsm4(ua, abase + mt * 16 * XSTR * 4);
            uint32_t ah[4];
            #pragma unroll
            for (int i = 0; i < 4; i++) ah[i] = f2tf32(__uint_as_float(ua[i]));
            #pragma unroll
            for (int nt = 0; nt < 3; nt++)
                mma_tf32(&cacc[(mt * 3 + nt) * 4], ah, &bh[2 * nt]);
        }

        __syncwarp();   // WAR: lanes done reading cur (LDSM crosses lanes)
        if (ch + 1 < NCH) {
            *reinterpret_cast<float4*>(&nxt[r0 * XSTR])     = make_float4(rr[0], rr[1], rr[2], rr[3]);
            *reinterpret_cast<float4*>(&nxt[r0 * XSTR + 4]) = make_float4(rr[4], rr[5], rr[6], rr[7]);
            *reinterpret_cast<float4*>(&nxt[r1 * XSTR])     = make_float4(rr[8], rr[9], rr[10], rr[11]);
            *reinterpret_cast<float4*>(&nxt[r1 * XSTR + 4]) = make_float4(rr[12], rr[13], rr[14], rr[15]);
        }
        __syncwarp();   // RAW: staged data visible
    }

    __syncthreads();   // all warps done with w_s before qkv overlay

    // ---- epilogue: C fragments -> qkv_s [256][28] ----
    float* qkv = smem;
    {
        const int erow = 64 * w + (l >> 2);
        const int ecol = 2 * (l & 3);
        #pragma unroll
        for (int mt = 0; mt < 4; mt++) {
            #pragma unroll
            for (int nt = 0; nt < 3; nt++) {
                const float* cf = &cacc[(mt * 3 + nt) * 4];
                float* p = &qkv[(erow + 16 * mt) * QKVSTR + nt * 8 + ecol];
                *reinterpret_cast<float2*>(p)               = make_float2(cf[0], cf[1]);
                *reinterpret_cast<float2*>(p + 8 * QKVSTR)  = make_float2(cf[2], cf[3]);
            }
        }
    }
    __syncthreads();

    // ---- phase 2: scalar causal attention (R12), q/k/v from qkv_s ----
    const int wblk = (w + b) & 3;            // SMSP balance
    const int t0 = 64 * wblk + 2 * l;
    const int t1 = t0 + 1;

    const float kScale = 1.4426950408889634f * rsqrtf((float)CC);
    const u64 sc2 = pack2(kScale);

    const float4 qa0 = *reinterpret_cast<const float4*>(&qkv[t0 * QKVSTR]);
    const float4 qb0 = *reinterpret_cast<const float4*>(&qkv[t0 * QKVSTR + 4]);
    const float4 qa1 = *reinterpret_cast<const float4*>(&qkv[t1 * QKVSTR]);
    const float4 qb1 = *reinterpret_cast<const float4*>(&qkv[t1 * QKVSTR + 4]);
    const u64 q00 = mul2(pack2f(qa0.x, qa0.y), sc2), q01 = mul2(pack2f(qa0.z, qa0.w), sc2);
    const u64 q02 = mul2(pack2f(qb0.x, qb0.y), sc2), q03 = mul2(pack2f(qb0.z, qb0.w), sc2);
    const u64 q10 = mul2(pack2f(qa1.x, qa1.y), sc2), q11 = mul2(pack2f(qa1.z, qa1.w), sc2);
    const u64 q12 = mul2(pack2f(qb1.x, qb1.y), sc2), q13 = mul2(pack2f(qb1.z, qb1.w), sc2);

    u64 o00 = 0, o01 = 0, o02 = 0, o03 = 0;
    u64 o10 = 0, o11 = 0, o12 = 0, o13 = 0;
    float ssum0 = 0.f, ssum1 = 0.f;

    const int kb0 = 64 * wblk;
    const float* kvp = qkv + 8;    // k at +8, v at +16 within each row

    // bulk prefix: no causal predication needed
    #pragma unroll 2
    for (int k = 0; k < kb0; k++) {
        const float* kr = kvp + k * QKVSTR;
        ulonglong2 ka = *reinterpret_cast<const ulonglong2*>(kr);        // 16B aligned
        u64 s0 = mul2(q00, ka.x); u64 s1 = mul2(q10, ka.x);
        ffma2(s0, q01, ka.y);     ffma2(s1, q11, ka.y);
        ulonglong2 kb = *reinterpret_cast<const ulonglong2*>(kr + 4);
        ffma2(s0, q02, kb.x);     ffma2(s1, q12, kb.x);
        ffma2(s0, q03, kb.y);     ffma2(s1, q13, kb.y);
        float a0, b0; unpack2(s0, a0, b0);
        float a1, b1; unpack2(s1, a1, b1);
        float p0 = exp2f(a0 + b0);
        float p1 = exp2f(a1 + b1);
        ssum0 += p0; ssum1 += p1;
        u64 pp0 = pack2(p0), pp1 = pack2(p1);
        ulonglong2 va = *reinterpret_cast<const ulonglong2*>(kr + 8);
        ulonglong2 vb = *reinterpret_cast<const ulonglong2*>(kr + 12);
        ffma2(o00, pp0, va.x); ffma2(o01, pp0, va.y);
        ffma2(o02, pp0, vb.x); ffma2(o03, pp0, vb.y);
        ffma2(o10, pp1, va.x); ffma2(o11, pp1, va.y);
        ffma2(o12, pp1, vb.x); ffma2(o13, pp1, vb.y);
    }

    // diagonal block: per-lane causal predication
    #pragma unroll 2
    for (int k = kb0; k < kb0 + 64; k++) {
        const float* kr = kvp + k * QKVSTR;
        ulonglong2 ka = *reinterpret_cast<const ulonglong2*>(kr);
        u64 s0 = mul2(q00, ka.x); u64 s1 = mul2(q10, ka.x);
        ffma2(s0, q01, ka.y);     ffma2(s1, q11, ka.y);
        ulonglong2 kb = *reinterpret_cast<const ulonglong2*>(kr + 4);
        ffma2(s0, q02, kb.x);     ffma2(s1, q12, kb.x);
        ffma2(s0, q03, kb.y);     ffma2(s1, q13, kb.y);
        float a0, b0; unpack2(s0, a0, b0);
        float a1, b1; unpack2(s1, a1, b1);
        float p0 = exp2f(a0 + b0);
        float p1 = exp2f(a1 + b1);
        p0 = (k <= t0) ? p0 : 0.f;
        p1 = (k <= t1) ? p1 : 0.f;
        ssum0 += p0; ssum1 += p1;
        u64 pp0 = pack2(p0), pp1 = pack2(p1);
        ulonglong2 va = *reinterpret_cast<const ulonglong2*>(kr + 8);
        ulonglong2 vb = *reinterpret_cast<const ulonglong2*>(kr + 12);
        ffma2(o00, pp0, va.x); ffma2(o01, pp0, va.y);
        ffma2(o02, pp0, vb.x); ffma2(o03, pp0, vb.y);
        ffma2(o10, pp1, va.x); ffma2(o11, pp1, va.y);
        ffma2(o12, pp1, vb.x); ffma2(o13, pp1, vb.y);
    }

    const u64 i0 = pack2(__fdividef(1.f, ssum0));
    const u64 i1 = pack2(__fdividef(1.f, ssum1));
    u64* op = reinterpret_cast<u64*>(out + ((long)b * TT + t0) * HH);
    op[0] = mul2(o00, i0); op[1] = mul2(o01, i0);
    op[2] = mul2(o02, i0); op[3] = mul2(o03, i0);
    op[4] = mul2(o10, i1); op[5] = mul2(o11, i1);
    op[6] = mul2(o12, i1); op[7] = mul2(o13, i1);
}

extern "C" void kernel_launch(void* const* d_in, const int* in_sizes, int n_in,
                              void* d_out, int out_size)
{
    const float* x  = (const float*)d_in[0];
    const float* Wq = (const float*)d_in[1];
    const float* Wk = (const float*)d_in[2];
    const float* Wv = (const float*)d_in[3];
    float* out = (float*)d_out;

    head_attn_kernel<<<1024, NT>>>(x, Wq, Wk, Wv, out);
}

// round 14
// speedup vs baseline: 1.5358x; 1.5358x over previous
#include <cuda_runtime.h>
#include <cstdint>

#define TT 256
#define CC 195
#define HH 8
#define JJ 24            // qkv cols: q(0-7) k(8-15) v(16-23)
#define NT 128
#define KPAD 200         // K padded to 25 chunks of 8
#define NCH 25
#define WFLOATS (KPAD * JJ)   // 4800
#define QKVSTR 28             // qkv smem row stride (112B, 16B-aligned rows)

typedef unsigned long long u64;

__device__ __forceinline__ u64 pack2(float v) {
    u64 r; asm("mov.b64 %0, {%1, %1};" : "=l"(r) : "f"(v)); return r;
}
__device__ __forceinline__ u64 pack2f(float lo, float hi) {
    u64 r; asm("mov.b64 %0, {%1, %2};" : "=l"(r) : "f"(lo), "f"(hi)); return r;
}
__device__ __forceinline__ void unpack2(u64 v, float& lo, float& hi) {
    asm("mov.b64 {%0, %1}, %2;" : "=f"(lo), "=f"(hi) : "l"(v));
}
__device__ __forceinline__ void ffma2(u64& d, u64 a, u64 b) {
    asm("fma.rn.f32x2 %0, %1, %2, %0;" : "+l"(d) : "l"(a), "l"(b));
}
__device__ __forceinline__ u64 mul2(u64 a, u64 b) {
    u64 r; asm("mul.rn.f32x2 %0, %1, %2;" : "=l"(r) : "l"(a), "l"(b)); return r;
}
__device__ __forceinline__ uint32_t f2tf32(float f) {
    uint32_t r; asm("cvt.rna.tf32.f32 %0, %1;" : "=r"(r) : "f"(f)); return r;
}
__device__ __forceinline__ void mma_tf32(float* c, const uint32_t* a, const uint32_t* b) {
    asm volatile("mma.sync.aligned.m16n8k8.row.col.f32.tf32.tf32.f32 "
                 "{%0,%1,%2,%3}, {%4,%5,%6,%7}, {%8,%9}, {%0,%1,%2,%3};"
                 : "+f"(c[0]), "+f"(c[1]), "+f"(c[2]), "+f"(c[3])
                 : "r"(a[0]), "r"(a[1]), "r"(a[2]), "r"(a[3]), "r"(b[0]), "r"(b[1]));
}

// A fragments for chunk starting at col c0: validated m16n8k8 mapping.
// Warp LDG footprint per instruction: 8 rows x 16B (clean 32B sectors; +4 col
// loads L1-hit the same sectors).
__device__ __forceinline__ void load_a_chunk(const float* __restrict__ xg,
                                             int c0, int ar, int ac,
                                             float* ra, bool tail) {
    #pragma unroll
    for (int mt = 0; mt < 4; mt++) {
        const float* p0 = xg + (long)(16 * mt + ar) * CC;
        const float* p1 = p0 + 8 * CC;
        if (!tail) {
            ra[4 * mt + 0] = __ldg(p0 + c0 + ac);
            ra[4 * mt + 1] = __ldg(p1 + c0 + ac);
            ra[4 * mt + 2] = __ldg(p0 + c0 + ac + 4);
            ra[4 * mt + 3] = __ldg(p1 + c0 + ac + 4);
        } else {
            const bool v0 = (c0 + ac) < CC;          // cols 192..194 only
            ra[4 * mt + 0] = v0 ? __ldg(p0 + c0 + ac) : 0.f;
            ra[4 * mt + 1] = v0 ? __ldg(p1 + c0 + ac) : 0.f;
            ra[4 * mt + 2] = 0.f;                    // c0+ac+4 >= 196 > 194
            ra[4 * mt + 3] = 0.f;
        }
    }
}

__global__ __launch_bounds__(NT, 4)
void head_attn_kernel(const float* __restrict__ x,
                      const float* __restrict__ Wq,
                      const float* __restrict__ Wk,
                      const float* __restrict__ Wv,
                      float* __restrict__ out)
{
    // phase A: w_s = tf32-converted W [KPAD][24] (19200B of the 28672B buffer)
    // phase B: qkv [256][28] f32 overlays the whole buffer
    __shared__ __align__(16) float smem[TT * QKVSTR];   // 7168 floats = 28672B
    float* w_s = smem;

    const int tid = threadIdx.x;
    const int b   = blockIdx.x;
    const int w   = tid >> 5;
    const int l   = tid & 31;

    // 1/sqrt(C)*log2(e) folded into Wq (pre-tf32) so phase 2 uses bare exp2
    const float kScale = 1.4426950408889634f * rsqrtf((float)CC);

    // ---- stage W as [c][24], tf32 bit patterns, K rows >= CC zeroed ----
    for (int i = tid; i < KPAD * HH; i += NT) {
        int c = i >> 3, h = i & 7;
        float vq = 0.f, vk = 0.f, vv = 0.f;
        if (c < CC) {
            vq = Wq[c * HH + h] * kScale;
            vk = Wk[c * HH + h];
            vv = Wv[c * HH + h];
        }
        w_s[c * JJ +      h] = __uint_as_float(f2tf32(vq));
        w_s[c * JJ +  8 + h] = __uint_as_float(f2tf32(vk));
        w_s[c * JJ + 16 + h] = __uint_as_float(f2tf32(vv));
    }
    __syncthreads();

    // ---- phase 1: tf32 MMA projection, direct-LDG A fragments ----
    const float* xg = x + ((long)b * TT + 64 * w) * CC;   // warp's 64-row block
    const int ar = l >> 2;   // A row within m16 tile
    const int ac = l & 3;    // A col within k8 chunk
    const int bk = l & 3;    // B k within chunk
    const int bn = l >> 2;   // B n within n8 tile

    float cacc[48];          // [mt 0..3][nt 0..2][4]
    #pragma unroll
    for (int i = 0; i < 48; i++) cacc[i] = 0.f;

    float ra[16], rb[16];
    load_a_chunk(xg, 0, ar, ac, ra, false);

    #pragma unroll 1
    for (int ch = 0; ch < NCH; ch++) {
        // prefetch next chunk's A fragments (independent LDGs, MLP=16)
        if (ch + 1 < NCH)
            load_a_chunk(xg, (ch + 1) * 8, ar, ac, rb, (ch + 1) == NCH - 1);

        // B fragments: pre-converted tf32 bits; banks 24*bk+bn all-distinct
        const int kr = ch * 8 + bk;
        uint32_t bh[6];
        #pragma unroll
        for (int nt = 0; nt < 3; nt++) {
            bh[2 * nt]     = __float_as_uint(w_s[kr * JJ       + nt * 8 + bn]);
            bh[2 * nt + 1] = __float_as_uint(w_s[(kr + 4) * JJ + nt * 8 + bn]);
        }

        // convert this chunk's A to tf32 and issue 12 MMAs
        #pragma unroll
        for (int mt = 0; mt < 4; mt++) {
            uint32_t ah[4];
            #pragma unroll
            for (int i = 0; i < 4; i++) ah[i] = f2tf32(ra[4 * mt + i]);
            #pragma unroll
            for (int nt = 0; nt < 3; nt++)
                mma_tf32(&cacc[(mt * 3 + nt) * 4], ah, &bh[2 * nt]);
        }

        #pragma unroll
        for (int i = 0; i < 16; i++) ra[i] = rb[i];
    }

    __syncthreads();   // all warps done reading w_s before qkv overlay

    // ---- epilogue: C fragments -> qkv [256][28] (validated mapping) ----
    float* qkv = smem;
    {
        const int erow = 64 * w + (l >> 2);
        const int ecol = 2 * (l & 3);
        #pragma unroll
        for (int mt = 0; mt < 4; mt++) {
            #pragma unroll
            for (int nt = 0; nt < 3; nt++) {
                const float* cf = &cacc[(mt * 3 + nt) * 4];
                float* p = &qkv[(erow + 16 * mt) * QKVSTR + nt * 8 + ecol];
                *reinterpret_cast<float2*>(p)              = make_float2(cf[0], cf[1]);
                *reinterpret_cast<float2*>(p + 8 * QKVSTR) = make_float2(cf[2], cf[3]);
            }
        }
    }
    __syncthreads();

    // ---- phase 2: scalar causal attention (R12 structure) ----
    const int wblk = (w + b) & 3;    // SMSP balance rotation
    const int t0 = 64 * wblk + 2 * l;
    const int t1 = t0 + 1;

    // q already carries kScale (folded into Wq before projection)
    const float4 qa0 = *reinterpret_cast<const float4*>(&qkv[t0 * QKVSTR]);
    const float4 qb0 = *reinterpret_cast<const float4*>(&qkv[t0 * QKVSTR + 4]);
    const float4 qa1 = *reinterpret_cast<const float4*>(&qkv[t1 * QKVSTR]);
    const float4 qb1 = *reinterpret_cast<const float4*>(&qkv[t1 * QKVSTR + 4]);
    const u64 q00 = pack2f(qa0.x, qa0.y), q01 = pack2f(qa0.z, qa0.w);
    const u64 q02 = pack2f(qb0.x, qb0.y), q03 = pack2f(qb0.z, qb0.w);
    const u64 q10 = pack2f(qa1.x, qa1.y), q11 = pack2f(qa1.z, qa1.w);
    const u64 q12 = pack2f(qb1.x, qb1.y), q13 = pack2f(qb1.z, qb1.w);

    u64 o00 = 0, o01 = 0, o02 = 0, o03 = 0;
    u64 o10 = 0, o11 = 0, o12 = 0, o13 = 0;
    float ssum0 = 0.f, ssum1 = 0.f;

    const int kb0 = 64 * wblk;
    const float* kvp = qkv + 8;    // k at +8, v at +16 within each row

    // bulk prefix: no causal predication needed (k < kb0 <= t0 < t1)
    #pragma unroll 2
    for (int k = 0; k < kb0; k++) {
        const float* kr = kvp + k * QKVSTR;
        ulonglong2 ka = *reinterpret_cast<const ulonglong2*>(kr);
        u64 s0 = mul2(q00, ka.x); u64 s1 = mul2(q10, ka.x);
        ffma2(s0, q01, ka.y);     ffma2(s1, q11, ka.y);
        ulonglong2 kb = *reinterpret_cast<const ulonglong2*>(kr + 4);
        ffma2(s0, q02, kb.x);     ffma2(s1, q12, kb.x);
        ffma2(s0, q03, kb.y);     ffma2(s1, q13, kb.y);
        float a0, b0; unpack2(s0, a0, b0);
        float a1, b1; unpack2(s1, a1, b1);
        float p0 = exp2f(a0 + b0);
        float p1 = exp2f(a1 + b1);
        ssum0 += p0; ssum1 += p1;
        u64 pp0 = pack2(p0), pp1 = pack2(p1);
        ulonglong2 va = *reinterpret_cast<const ulonglong2*>(kr + 8);
        ulonglong2 vb = *reinterpret_cast<const ulonglong2*>(kr + 12);
        ffma2(o00, pp0, va.x); ffma2(o01, pp0, va.y);
        ffma2(o02, pp0, vb.x); ffma2(o03, pp0, vb.y);
        ffma2(o10, pp1, va.x); ffma2(o11, pp1, va.y);
        ffma2(o12, pp1, vb.x); ffma2(o13, pp1, vb.y);
    }

    // diagonal block: per-lane causal predication
    #pragma unroll 2
    for (int k = kb0; k < kb0 + 64; k++) {
        const float* kr = kvp + k * QKVSTR;
        ulonglong2 ka = *reinterpret_cast<const ulonglong2*>(kr);
        u64 s0 = mul2(q00, ka.x); u64 s1 = mul2(q10, ka.x);
        ffma2(s0, q01, ka.y);     ffma2(s1, q11, ka.y);
        ulonglong2 kb = *reinterpret_cast<const ulonglong2*>(kr + 4);
        ffma2(s0, q02, kb.x);     ffma2(s1, q12, kb.x);
        ffma2(s0, q03, kb.y);     ffma2(s1, q13, kb.y);
        float a0, b0; unpack2(s0, a0, b0);
        float a1, b1; unpack2(s1, a1, b1);
        float p0 = exp2f(a0 + b0);
        float p1 = exp2f(a1 + b1);
        p0 = (k <= t0) ? p0 : 0.f;
        p1 = (k <= t1) ? p1 : 0.f;
        ssum0 += p0; ssum1 += p1;
        u64 pp0 = pack2(p0), pp1 = pack2(p1);
        ulonglong2 va = *reinterpret_cast<const ulonglong2*>(kr + 8);
        ulonglong2 vb = *reinterpret_cast<const ulonglong2*>(kr + 12);
        ffma2(o00, pp0, va.x); ffma2(o01, pp0, va.y);
        ffma2(o02, pp0, vb.x); ffma2(o03, pp0, vb.y);
        ffma2(o10, pp1, va.x); ffma2(o11, pp1, va.y);
        ffma2(o12, pp1, vb.x); ffma2(o13, pp1, vb.y);
    }

    const u64 i0 = pack2(__fdividef(1.f, ssum0));
    const u64 i1 = pack2(__fdividef(1.f, ssum1));
    u64* op = reinterpret_cast<u64*>(out + ((long)b * TT + t0) * HH);
    op[0] = mul2(o00, i0); op[1] = mul2(o01, i0);
    op[2] = mul2(o02, i0); op[3] = mul2(o03, i0);
    op[4] = mul2(o10, i1); op[5] = mul2(o11, i1);
    op[6] = mul2(o12, i1); op[7] = mul2(o13, i1);
}

extern "C" void kernel_launch(void* const* d_in, const int* in_sizes, int n_in,
                              void* d_out, int out_size)
{
    const float* x  = (const float*)d_in[0];
    const float* Wq = (const float*)d_in[1];
    const float* Wk = (const float*)d_in[2];
    const float* Wv = (const float*)d_in[3];
    float* out = (float*)d_out;

    head_attn_kernel<<<1024, NT>>>(x, Wq, Wk, Wv, out);
}

// round 15
// speedup vs baseline: 1.7712x; 1.1532x over previous
#include <cuda_runtime.h>
#include <cstdint>

#define TT 256
#define CC 195
#define HH 8
#define JJ 24            // qkv cols: q(0-7) k(8-15) v(16-23)
#define NT 128
#define KPAD 200
#define NCH 25
#define QKVSTR 28        // qkv smem row stride (112B, 16B-aligned, LDSM banks -4r%32 distinct)
#define PSTR 12          // P buffer row stride (48B, LDSM banks 12r%32 distinct)
#define PBUF (64 * PSTR) // 768 floats per warp

typedef unsigned long long u64;

__device__ __forceinline__ uint32_t f2tf32(float f) {
    uint32_t r; asm("cvt.rna.tf32.f32 %0, %1;" : "=r"(r) : "f"(f)); return r;
}
__device__ __forceinline__ void ldsm4(uint32_t* d, unsigned addr) {
    asm volatile("ldmatrix.sync.aligned.m8n8.x4.shared.b16 {%0,%1,%2,%3}, [%4];"
                 : "=r"(d[0]), "=r"(d[1]), "=r"(d[2]), "=r"(d[3]) : "r"(addr));
}
__device__ __forceinline__ void mma_tf32(float* c, const uint32_t* a, const uint32_t* b) {
    asm volatile("mma.sync.aligned.m16n8k8.row.col.f32.tf32.tf32.f32 "
                 "{%0,%1,%2,%3}, {%4,%5,%6,%7}, {%8,%9}, {%0,%1,%2,%3};"
                 : "+f"(c[0]), "+f"(c[1]), "+f"(c[2]), "+f"(c[3])
                 : "r"(a[0]), "r"(a[1]), "r"(a[2]), "r"(a[3]), "r"(b[0]), "r"(b[1]));
}

// validated A-fragment gmem mapping (R14)
__device__ __forceinline__ void load_a_chunk(const float* __restrict__ xg,
                                             int c0, int ar, int ac,
                                             float* ra, bool tail) {
    #pragma unroll
    for (int mt = 0; mt < 4; mt++) {
        const float* p0 = xg + (long)(16 * mt + ar) * CC;
        const float* p1 = p0 + 8 * CC;
        if (!tail) {
            ra[4 * mt + 0] = __ldg(p0 + c0 + ac);
            ra[4 * mt + 1] = __ldg(p1 + c0 + ac);
            ra[4 * mt + 2] = __ldg(p0 + c0 + ac + 4);
            ra[4 * mt + 3] = __ldg(p1 + c0 + ac + 4);
        } else {
            const bool v0 = (c0 + ac) < CC;
            ra[4 * mt + 0] = v0 ? __ldg(p0 + c0 + ac) : 0.f;
            ra[4 * mt + 1] = v0 ? __ldg(p1 + c0 + ac) : 0.f;
            ra[4 * mt + 2] = 0.f;
            ra[4 * mt + 3] = 0.f;
        }
    }
}

__global__ __launch_bounds__(NT, 4)
void head_attn_kernel(const float* __restrict__ x,
                      const float* __restrict__ Wq,
                      const float* __restrict__ Wk,
                      const float* __restrict__ Wv,
                      float* __restrict__ out)
{
    // [ qkv/w_s region: 7168 floats | 4 x warp P buffer: 768 floats ] = 40960B
    __shared__ __align__(16) float smem[TT * QKVSTR + 4 * PBUF];
    float* w_s = smem;

    const int tid = threadIdx.x;
    const int b   = blockIdx.x;
    const int w   = tid >> 5;
    const int l   = tid & 31;

    const float kScale = 1.4426950408889634f * rsqrtf((float)CC);  // 1/sqrt(C)*log2(e)

    // ---- stage W as [c][24], tf32 bits, K rows >= CC zeroed ----
    for (int i = tid; i < KPAD * HH; i += NT) {
        int c = i >> 3, h = i & 7;
        float vq = 0.f, vk = 0.f, vv = 0.f;
        if (c < CC) {
            vq = Wq[c * HH + h] * kScale;
            vk = Wk[c * HH + h];
            vv = Wv[c * HH + h];
        }
        w_s[c * JJ +      h] = __uint_as_float(f2tf32(vq));
        w_s[c * JJ +  8 + h] = __uint_as_float(f2tf32(vk));
        w_s[c * JJ + 16 + h] = __uint_as_float(f2tf32(vv));
    }
    __syncthreads();

    // ---- phase 1: tf32 MMA projection, direct-LDG A fragments (R14) ----
    const float* xg = x + ((long)b * TT + 64 * w) * CC;
    const int ar = l >> 2;
    const int ac = l & 3;
    const int bn = l >> 2;   // B n index
    const int bk = l & 3;    // B k index

    float cacc[48];
    #pragma unroll
    for (int i = 0; i < 48; i++) cacc[i] = 0.f;

    float ra[16], rb[16];
    load_a_chunk(xg, 0, ar, ac, ra, false);

    #pragma unroll 1
    for (int ch = 0; ch < NCH; ch++) {
        if (ch + 1 < NCH)
            load_a_chunk(xg, (ch + 1) * 8, ar, ac, rb, (ch + 1) == NCH - 1);

        const int kr = ch * 8 + bk;
        uint32_t bh[6];
        #pragma unroll
        for (int nt = 0; nt < 3; nt++) {
            bh[2 * nt]     = __float_as_uint(w_s[kr * JJ       + nt * 8 + bn]);
            bh[2 * nt + 1] = __float_as_uint(w_s[(kr + 4) * JJ + nt * 8 + bn]);
        }
        #pragma unroll
        for (int mt = 0; mt < 4; mt++) {
            uint32_t ah[4];
            #pragma unroll
            for (int i = 0; i < 4; i++) ah[i] = f2tf32(ra[4 * mt + i]);
            #pragma unroll
            for (int nt = 0; nt < 3; nt++)
                mma_tf32(&cacc[(mt * 3 + nt) * 4], ah, &bh[2 * nt]);
        }
        #pragma unroll
        for (int i = 0; i < 16; i++) ra[i] = rb[i];
    }

    __syncthreads();   // w_s reads done before qkv overlay

    // ---- epilogue: C fragments -> qkv [256][28] (validated) ----
    float* qkv = smem;
    {
        const int erow = 64 * w + (l >> 2);
        const int ecol = 2 * (l & 3);
        #pragma unroll
        for (int mt = 0; mt < 4; mt++) {
            #pragma unroll
            for (int nt = 0; nt < 3; nt++) {
                const float* cf = &cacc[(mt * 3 + nt) * 4];
                float* p = &qkv[(erow + 16 * mt) * QKVSTR + nt * 8 + ecol];
                *reinterpret_cast<float2*>(p)              = make_float2(cf[0], cf[1]);
                *reinterpret_cast<float2*>(p + 8 * QKVSTR) = make_float2(cf[2], cf[3]);
            }
        }
    }
    __syncthreads();

    // ---- phase 2: tensor-core causal attention, per-warp 64-row block ----
    const int wblk = (w + b) & 3;          // SMSP balance rotation
    float* pbuf = smem + TT * QKVSTR + w * PBUF;   // warp-private P tile [64][12]

    // LDSM lane addressing (validated R13 geometry)
    const unsigned lrow  = (l & 7) + 8 * ((l >> 3) & 1);
    const unsigned lcolo = (l >> 4) * 16;
    const unsigned qbase = (unsigned)__cvta_generic_to_shared(qkv)
                         + (64 * wblk + lrow) * (QKVSTR * 4) + lcolo;
    const unsigned pbase = (unsigned)__cvta_generic_to_shared(pbuf)
                         + lrow * (PSTR * 4) + lcolo;

    // Q A-fragments: loaded once (K=8 total for the score GEMM)
    uint32_t qa[16];
    #pragma unroll
    for (int mt = 0; mt < 4; mt++) {
        uint32_t u[4];
        ldsm4(u, qbase + mt * 16 * QKVSTR * 4);
        #pragma unroll
        for (int i = 0; i < 4; i++) qa[4 * mt + i] = f2tf32(__uint_as_float(u[i]));
    }

    float oacc[16];   // AV accumulators [mt][4]
    float ssum[8];    // row sums: [mt][delta]
    #pragma unroll
    for (int i = 0; i < 16; i++) oacc[i] = 0.f;
    #pragma unroll
    for (int i = 0; i < 8; i++) ssum[i] = 0.f;

    const int nkc  = 8 * (wblk + 1);   // key chunks (8 keys each)
    const int dkc  = 8 * wblk;         // first diagonal chunk
    const int r1b  = 64 * wblk + (l >> 2);   // lane's row for delta=0 (per mt: +16mt)
    const int keyc = 2 * (l & 3);            // lane's key col within n8 tile

    #pragma unroll 1
    for (int kc = 0; kc < nkc; kc++) {
        // S = Q*K^T for this 8-key chunk. B: K[key n][dim k] (banks all-distinct)
        const int krow = 8 * kc + (l >> 2);
        uint32_t sb[2];
        sb[0] = f2tf32(qkv[krow * QKVSTR + 8 + (l & 3)]);
        sb[1] = f2tf32(qkv[krow * QKVSTR + 8 + (l & 3) + 4]);

        float sfr[16];
        #pragma unroll
        for (int i = 0; i < 16; i++) sfr[i] = 0.f;
        #pragma unroll
        for (int mt = 0; mt < 4; mt++)
            mma_tf32(&sfr[4 * mt], &qa[4 * mt], sb);

        // exp2 (+ causal mask on diagonal chunks), row-sum, P -> warp buffer
        const int key0 = 8 * kc + keyc;
        const bool diag = (kc >= dkc);
        #pragma unroll
        for (int mt = 0; mt < 4; mt++) {
            const int rr1 = r1b + 16 * mt, rr2 = rr1 + 8;
            float p0 = exp2f(sfr[4 * mt + 0]);
            float p1 = exp2f(sfr[4 * mt + 1]);
            float p2 = exp2f(sfr[4 * mt + 2]);
            float p3 = exp2f(sfr[4 * mt + 3]);
            if (diag) {
                p0 = (key0     <= rr1) ? p0 : 0.f;
                p1 = (key0 + 1 <= rr1) ? p1 : 0.f;
                p2 = (key0     <= rr2) ? p2 : 0.f;
                p3 = (key0 + 1 <= rr2) ? p3 : 0.f;
            }
            ssum[2 * mt]     += p0 + p1;
            ssum[2 * mt + 1] += p2 + p3;
            float* pp = &pbuf[(16 * mt + (l >> 2)) * PSTR + keyc];
            *reinterpret_cast<float2*>(pp)            = make_float2(p0, p1);
            *reinterpret_cast<float2*>(pp + 8 * PSTR) = make_float2(p2, p3);
        }
        __syncwarp();   // P visible to all lanes

        // AV: A = P chunk (LDSM), B = V[key k][head n]
        uint32_t vb[2];
        vb[0] = f2tf32(qkv[(8 * kc + (l & 3)) * QKVSTR + 16 + (l >> 2)]);
        vb[1] = f2tf32(qkv[(8 * kc + (l & 3) + 4) * QKVSTR + 16 + (l >> 2)]);
        #pragma unroll
        for (int mt = 0; mt < 4; mt++) {
            uint32_t u[4], pa[4];
            ldsm4(u, pbase + mt * 16 * PSTR * 4);
            #pragma unroll
            for (int i = 0; i < 4; i++) pa[i] = f2tf32(__uint_as_float(u[i]));
            mma_tf32(&oacc[4 * mt], pa, vb);
        }
        __syncwarp();   // WAR before next chunk overwrites pbuf
    }

    // reduce row sums across the quad (lanes sharing l>>2)
    #pragma unroll
    for (int i = 0; i < 8; i++) {
        ssum[i] += __shfl_xor_sync(0xFFFFFFFF, ssum[i], 1);
        ssum[i] += __shfl_xor_sync(0xFFFFFFFF, ssum[i], 2);
    }

    // normalize + write O directly from C fragments (float2 per row pair)
    float* ob = out + (long)b * TT * HH;
    #pragma unroll
    for (int mt = 0; mt < 4; mt++) {
        const int rr1 = r1b + 16 * mt;
        const float i1 = __fdividef(1.f, ssum[2 * mt]);
        const float i2 = __fdividef(1.f, ssum[2 * mt + 1]);
        *reinterpret_cast<float2*>(&ob[rr1 * HH + keyc]) =
            make_float2(oacc[4 * mt + 0] * i1, oacc[4 * mt + 1] * i1);
        *reinterpret_cast<float2*>(&ob[(rr1 + 8) * HH + keyc]) =
            make_float2(oacc[4 * mt + 2] * i2, oacc[4 * mt + 3] * i2);
    }
}

extern "C" void kernel_launch(void* const* d_in, const int* in_sizes, int n_in,
                              void* d_out, int out_size)
{
    const float* x  = (const float*)d_in[0];
    const float* Wq = (const float*)d_in[1];
    const float* Wk = (const float*)d_in[2];
    const float* Wv = (const float*)d_in[3];
    float* out = (float*)d_out;

    head_attn_kernel<<<1024, NT>>>(x, Wq, Wk, Wv, out);
}